// round 1
// baseline (speedup 1.0000x reference)
#include <cuda_runtime.h>
#include <cstdint>

#define S_LEN 2048
#define BATCH 256
#define INSZ  32
#define HID   8
#define G4    32          // 4*HID gates
#define NBLK  80
#define OUTSZ 128
#define NROWS (S_LEN*BATCH)   // 524288

// Scratch (allowed: __device__ globals, no runtime allocation)
__device__ float g_xg[(size_t)NROWS * G4];   // 64 MB: x@W_ih^T + bias, pre-scaled
__device__ float g_ys[(size_t)NROWS * HID];  // 16 MB: LSTM hidden outputs

__device__ __forceinline__ float rcpa(float x) {
    float r; asm("rcp.approx.f32 %0, %1;" : "=f"(r) : "f"(x)); return r;
}
__device__ __forceinline__ float leaky(float v) { return fmaxf(v, 0.01f * v); }
__device__ __forceinline__ float fsig(float x)  { return rcpa(1.f + __expf(-x)); }

// ---------------------------------------------------------------------------
// K1: xg[row][g] = scale(g) * ( x[row] . w_ih[g] + b_ih[g] + b_hh[g] )
//     scale = 2 for the tanh gate (type 2), 1 for sigmoid gates.
//     One warp per row; lane = gate; x broadcast via shfl.
// ---------------------------------------------------------------------------
__global__ void __launch_bounds__(256) k1_xw(
    const float* __restrict__ x, const float* __restrict__ w_ih,
    const float* __restrict__ b_ih, const float* __restrict__ b_hh)
{
    const int lane = threadIdx.x & 31;
    const int wid  = (blockIdx.x * blockDim.x + threadIdx.x) >> 5;
    const int nw   = (gridDim.x * blockDim.x) >> 5;

    const float scale = ((lane >> 3) == 2) ? 2.f : 1.f;
    float w[32];
#pragma unroll
    for (int j = 0; j < 32; j++) w[j] = w_ih[lane * 32 + j] * scale;
    const float bias = (b_ih[lane] + b_hh[lane]) * scale;

    for (int row = wid; row < NROWS; row += nw) {
        const float xv = x[(size_t)row * 32 + lane];
        float a0 = bias, a1 = 0.f, a2 = 0.f, a3 = 0.f;
#pragma unroll
        for (int j = 0; j < 32; j += 4) {
            a0 = fmaf(w[j + 0], __shfl_sync(0xffffffffu, xv, j + 0), a0);
            a1 = fmaf(w[j + 1], __shfl_sync(0xffffffffu, xv, j + 1), a1);
            a2 = fmaf(w[j + 2], __shfl_sync(0xffffffffu, xv, j + 2), a2);
            a3 = fmaf(w[j + 3], __shfl_sync(0xffffffffu, xv, j + 3), a3);
        }
        g_xg[(size_t)row * 32 + lane] = (a0 + a1) + (a2 + a3);
    }
}

// ---------------------------------------------------------------------------
// K2: sequential LSTM. One warp per batch element. lane = gate index.
//     (c,h) replicated 4x across the warp (unit = lane&7), so every lane
//     holds a correct copy and all shuffles read valid data.
//     Activations: r = 1/(1+exp(-acc)); v = fma(r, A, B)
//       sigmoid gates: acc = z      -> A=1, B=0
//       tanh gate:     acc = 2z     -> A=2, B=-1   (tanh z = 2*sigmoid(2z)-1)
// ---------------------------------------------------------------------------
#define PF 8
__global__ void __launch_bounds__(32, 1) k2_lstm(
    const float* __restrict__ h0, const float* __restrict__ c0,
    const float* __restrict__ w_hh, float* __restrict__ out)
{
    const int lane = threadIdx.x;
    const int b    = blockIdx.x;
    const int unit = lane & 7;
    const bool tanh_gate = ((lane >> 3) == 2);
    const float scale = tanh_gate ? 2.f : 1.f;
    const float Am = tanh_gate ? 2.f : 1.f;
    const float Bm = tanh_gate ? -1.f : 0.f;

    float whh[8];
#pragma unroll
    for (int j = 0; j < 8; j++) whh[j] = w_hh[lane * 8 + j] * scale;

    float h = h0[b * 8 + unit];
    float c = c0[b * 8 + unit];

    const float* xp = g_xg + b * 32 + lane;     // stride per step: BATCH*32
    float* yp = g_ys + b * 8 + unit;            // stride per step: BATCH*8

    float buf[PF];
#pragma unroll
    for (int k = 0; k < PF; k++) buf[k] = __ldg(xp + (size_t)k * (BATCH * 32));

    for (int t = 0; t < S_LEN; t += PF) {
#pragma unroll
        for (int k = 0; k < PF; k++) {
            float a0 = buf[k], a1 = 0.f;
#pragma unroll
            for (int j = 0; j < 8; j += 2) {
                a0 = fmaf(whh[j + 0], __shfl_sync(0xffffffffu, h, j + 0), a0);
                a1 = fmaf(whh[j + 1], __shfl_sync(0xffffffffu, h, j + 1), a1);
            }
            const float acc = a0 + a1;
            const float v = fmaf(rcpa(1.f + __expf(-acc)), Am, Bm);

            const float iv = __shfl_sync(0xffffffffu, v, unit);
            const float fv = __shfl_sync(0xffffffffu, v, unit + 8);
            const float gv = __shfl_sync(0xffffffffu, v, unit + 16);
            const float ov = __shfl_sync(0xffffffffu, v, unit + 24);

            c = fmaf(fv, c, iv * gv);
            const float th = fmaf(rcpa(1.f + __expf(-2.f * c)), 2.f, -1.f);
            h = ov * th;

            const int t2 = t + k;
            if (lane < 8) yp[(size_t)t2 * (BATCH * 8)] = h;
            if (t2 + PF < S_LEN)
                buf[k] = __ldg(xp + (size_t)(t2 + PF) * (BATCH * 32));
        }
    }
    if (lane < 8) {
        out[(size_t)NROWS * OUTSZ + b * 8 + lane] = h;                 // h_f
        out[(size_t)NROWS * OUTSZ + BATCH * HID + b * 8 + lane] = c;   // c_f
    }
}

// ---------------------------------------------------------------------------
// K3: residual MLP head. One lane per (t,b) element for the 80-block chain
//     (weights staged in smem, broadcast LDS.128), then warp-transpose via
//     shfl so the 128-wide expansion writes coalesced STG.128.
// ---------------------------------------------------------------------------
struct RB { float4 w1; float4 w2; float4 b2; float b1; };

__global__ void __launch_bounds__(256) k3_res(
    const float* __restrict__ w_in,  const float* __restrict__ b_in,
    const float* __restrict__ rb_w1, const float* __restrict__ rb_b1,
    const float* __restrict__ rb_w2, const float* __restrict__ rb_b2,
    const float* __restrict__ w_bn,  const float* __restrict__ b_bn,
    const float* __restrict__ w_out, const float* __restrict__ b_out,
    float* __restrict__ out)
{
    __shared__ RB srb[NBLK];
    for (int i = threadIdx.x; i < NBLK; i += blockDim.x) {
        srb[i].w1 = make_float4(rb_w1[i*4+0], rb_w1[i*4+1], rb_w1[i*4+2], rb_w1[i*4+3]);
        srb[i].w2 = make_float4(rb_w2[i*4+0], rb_w2[i*4+1], rb_w2[i*4+2], rb_w2[i*4+3]);
        srb[i].b2 = make_float4(rb_b2[i*4+0], rb_b2[i*4+1], rb_b2[i*4+2], rb_b2[i*4+3]);
        srb[i].b1 = rb_b1[i];
    }
    __syncthreads();

    const int lane  = threadIdx.x & 31;
    const int warpg = (blockIdx.x * blockDim.x + threadIdx.x) >> 5;
    const int base  = warpg * 32;           // 16384 warps cover 524288 rows
    const int e     = base + lane;

    const float4 ha = *(const float4*)(g_ys + (size_t)e * 8);
    const float4 hb = *(const float4*)(g_ys + (size_t)e * 8 + 4);
    float hv[8] = {ha.x, ha.y, ha.z, ha.w, hb.x, hb.y, hb.z, hb.w};

    float y[4];
#pragma unroll
    for (int i = 0; i < 4; i++) {
        float a = b_in[i];
#pragma unroll
        for (int j = 0; j < 8; j++) a = fmaf(w_in[i * 8 + j], hv[j], a);
        y[i] = leaky(a);
    }

#pragma unroll 4
    for (int blk = 0; blk < NBLK; blk++) {
        const RB p = srb[blk];
        float z = p.b1;
        z = fmaf(p.w1.x, y[0], z);
        z = fmaf(p.w1.y, y[1], z);
        z = fmaf(p.w1.z, y[2], z);
        z = fmaf(p.w1.w, y[3], z);
        z = leaky(z);
        y[0] = leaky(fmaf(p.w2.x, z, y[0]) + p.b2.x);
        y[1] = leaky(fmaf(p.w2.y, z, y[1]) + p.b2.y);
        y[2] = leaky(fmaf(p.w2.z, z, y[2]) + p.b2.z);
        y[3] = leaky(fmaf(p.w2.w, z, y[3]) + p.b2.w);
    }

    float yb = b_bn[0];
    yb = fmaf(w_bn[0], y[0], yb);
    yb = fmaf(w_bn[1], y[1], yb);
    yb = fmaf(w_bn[2], y[2], yb);
    yb = fmaf(w_bn[3], y[3], yb);
    yb = leaky(yb);

    const float4 wo = *(const float4*)(w_out + lane * 4);
    const float4 bo = *(const float4*)(b_out + lane * 4);
    float* op = out + (size_t)base * OUTSZ + lane * 4;

#pragma unroll
    for (int cidx = 0; cidx < 32; cidx++) {
        const float ybc = __shfl_sync(0xffffffffu, yb, cidx);
        float4 o;
        o.x = fsig(fmaf(ybc, wo.x, bo.x));
        o.y = fsig(fmaf(ybc, wo.y, bo.y));
        o.z = fsig(fmaf(ybc, wo.z, bo.z));
        o.w = fsig(fmaf(ybc, wo.w, bo.w));
        *(float4*)(op + (size_t)cidx * OUTSZ) = o;
    }
}

// ---------------------------------------------------------------------------
extern "C" void kernel_launch(void* const* d_in, const int* in_sizes, int n_in,
                              void* d_out, int out_size)
{
    const float* x     = (const float*)d_in[0];
    const float* h     = (const float*)d_in[1];
    const float* c     = (const float*)d_in[2];
    const float* w_ih  = (const float*)d_in[3];
    const float* w_hh  = (const float*)d_in[4];
    const float* b_ih  = (const float*)d_in[5];
    const float* b_hh  = (const float*)d_in[6];
    const float* w_in  = (const float*)d_in[7];
    const float* b_in  = (const float*)d_in[8];
    const float* rb_w1 = (const float*)d_in[9];
    const float* rb_b1 = (const float*)d_in[10];
    const float* rb_w2 = (const float*)d_in[11];
    const float* rb_b2 = (const float*)d_in[12];
    const float* w_bn  = (const float*)d_in[13];
    const float* b_bn  = (const float*)d_in[14];
    const float* w_out = (const float*)d_in[15];
    const float* b_out = (const float*)d_in[16];
    float* out = (float*)d_out;

    k1_xw<<<512, 256>>>(x, w_ih, b_ih, b_hh);
    k2_lstm<<<BATCH, 32>>>(h, c, w_hh, out);
    k3_res<<<2048, 256>>>(w_in, b_in, rb_w1, rb_b1, rb_w2, rb_b2,
                          w_bn, b_bn, w_out, b_out, out);
}

// round 2
// speedup vs baseline: 1.5432x; 1.5432x over previous
#include <cuda_runtime.h>
#include <cstdint>

#define S_LEN 2048
#define BATCH 256
#define INSZ  32
#define HID   8
#define G4    32          // 4*HID gates
#define NBLK  80
#define OUTSZ 128
#define NROWS (S_LEN*BATCH)   // 524288

// Scratch (__device__ globals; no runtime allocation)
__device__ float g_xg[(size_t)NROWS * G4];   // 64 MB: x@W_ih^T + bias, pre-scaled (0.5x for sigmoid gates)
__device__ float g_ys[(size_t)NROWS * HID];  // 16 MB: LSTM hidden outputs

__device__ __forceinline__ float tanha(float x) {
    float r; asm("tanh.approx.f32 %0, %1;" : "=f"(r) : "f"(x)); return r;
}
__device__ __forceinline__ float leaky(float v) { return fmaxf(v, 0.01f * v); }

// ---------------------------------------------------------------------------
// K1: xg[row][g] = s(g) * ( x[row].w_ih[g] + b_ih[g] + b_hh[g] )
//     s = 0.5 for sigmoid gates (i,f,o), 1.0 for the tanh gate (g).
//     (so K2's activation is a bare tanh.approx: sigmoid(z)=0.5+0.5*tanh(z/2))
//     Thread-per-row; weights broadcast from smem (LDS.128, conflict-free).
// ---------------------------------------------------------------------------
__global__ void __launch_bounds__(256) k1_xw(
    const float* __restrict__ x, const float* __restrict__ w_ih,
    const float* __restrict__ b_ih, const float* __restrict__ b_hh)
{
    __shared__ float4 sw[32 * 8];   // [gate][j4]
    __shared__ float  sb[32];

    {
        const int idx = threadIdx.x;          // 256 threads: one float4 each
        const int g = idx >> 3;
        const float s = ((g >> 3) == 2) ? 1.f : 0.5f;
        float4 w4 = ((const float4*)w_ih)[idx];
        w4.x *= s; w4.y *= s; w4.z *= s; w4.w *= s;
        sw[idx] = w4;
        if (idx < 32) {
            const float s2 = ((idx >> 3) == 2) ? 1.f : 0.5f;
            sb[idx] = (b_ih[idx] + b_hh[idx]) * s2;
        }
    }
    __syncthreads();

    const int row = blockIdx.x * 256 + threadIdx.x;   // grid = 2048 blocks

    float4 xr[8];
#pragma unroll
    for (int j = 0; j < 8; j++) xr[j] = ((const float4*)x)[(size_t)row * 8 + j];

    float4* op = ((float4*)g_xg) + (size_t)row * 8;

#pragma unroll
    for (int gq = 0; gq < 8; gq++) {          // 4 gates at a time -> STG.128
        float4 o;
        float* po = &o.x;
#pragma unroll
        for (int gi = 0; gi < 4; gi++) {
            const int g = gq * 4 + gi;
            const float4* wp = &sw[g * 8];
            float a0 = sb[g], a1 = 0.f, a2 = 0.f, a3 = 0.f;
#pragma unroll
            for (int j = 0; j < 8; j++) {
                const float4 w4 = wp[j];
                const float4 x4 = xr[j];
                a0 = fmaf(w4.x, x4.x, a0);
                a1 = fmaf(w4.y, x4.y, a1);
                a2 = fmaf(w4.z, x4.z, a2);
                a3 = fmaf(w4.w, x4.w, a3);
            }
            po[gi] = (a0 + a1) + (a2 + a3);
        }
        op[gq] = o;
    }
}

// ---------------------------------------------------------------------------
// K2: sequential LSTM. One warp per batch element, lane = gate (4 types x 8 units).
//     (c,h) replicated 4x across the warp (unit = lane&7).
//     acc already pre-scaled: sigmoid gates hold z/2, g gate holds z.
//     v = tanh.approx(acc); sigmoid gate = fma(v, 0.5, 0.5); g gate = v.
// ---------------------------------------------------------------------------
#define PF 8
__global__ void __launch_bounds__(32, 1) k2_lstm(
    const float* __restrict__ h0, const float* __restrict__ c0,
    const float* __restrict__ w_hh, float* __restrict__ out)
{
    const int lane = threadIdx.x;
    const int b    = blockIdx.x;
    const int unit = lane & 7;
    const float scale = ((lane >> 3) == 2) ? 1.f : 0.5f;

    float whh[8];
#pragma unroll
    for (int j = 0; j < 8; j++) whh[j] = w_hh[lane * 8 + j] * scale;

    float h = h0[b * 8 + unit];
    float c = c0[b * 8 + unit];

    const float* xp = g_xg + b * 32 + lane;     // step stride: BATCH*32
    float* yp = g_ys + b * 8 + unit;            // step stride: BATCH*8

    float buf[PF];
#pragma unroll
    for (int k = 0; k < PF; k++) buf[k] = __ldg(xp + (size_t)k * (BATCH * 32));

    for (int t = 0; t < S_LEN; t += PF) {
#pragma unroll
        for (int k = 0; k < PF; k++) {
            // dot: 4 accumulators, 2-deep FMA + add tree
            float a0 = buf[k], a1 = 0.f, a2 = 0.f, a3 = 0.f;
            a0 = fmaf(whh[0], __shfl_sync(0xffffffffu, h, 0), a0);
            a1 = fmaf(whh[1], __shfl_sync(0xffffffffu, h, 1), a1);
            a2 = fmaf(whh[2], __shfl_sync(0xffffffffu, h, 2), a2);
            a3 = fmaf(whh[3], __shfl_sync(0xffffffffu, h, 3), a3);
            a0 = fmaf(whh[4], __shfl_sync(0xffffffffu, h, 4), a0);
            a1 = fmaf(whh[5], __shfl_sync(0xffffffffu, h, 5), a1);
            a2 = fmaf(whh[6], __shfl_sync(0xffffffffu, h, 6), a2);
            a3 = fmaf(whh[7], __shfl_sync(0xffffffffu, h, 7), a3);
            const float acc = (a0 + a1) + (a2 + a3);

            const float v = tanha(acc);

            const float iv = __shfl_sync(0xffffffffu, v, unit);
            const float fv = __shfl_sync(0xffffffffu, v, unit + 8);
            const float gv = __shfl_sync(0xffffffffu, v, unit + 16);
            const float ov = __shfl_sync(0xffffffffu, v, unit + 24);

            const float fg = fmaf(fv, 0.5f, 0.5f);
            const float ig = fmaf(iv, 0.5f, 0.5f);
            const float og = fmaf(ov, 0.5f, 0.5f);

            c = fmaf(fg, c, ig * gv);
            h = og * tanha(c);

            const int t2 = t + k;
            if (lane < 8) yp[(size_t)t2 * (BATCH * 8)] = h;
            if (t2 + PF < S_LEN)
                buf[k] = __ldg(xp + (size_t)(t2 + PF) * (BATCH * 32));
        }
    }
    if (lane < 8) {
        out[(size_t)NROWS * OUTSZ + b * 8 + lane] = h;                 // h_f
        out[(size_t)NROWS * OUTSZ + BATCH * HID + b * 8 + lane] = c;   // c_f
    }
}

// ---------------------------------------------------------------------------
// K3: residual MLP head. Lane per (t,b) row through the 80-block chain
//     (float4 smem weights, broadcast LDS.128), warp-transpose via shfl for
//     the 128-wide expansion -> coalesced STG.128. Sigmoid via tanh.approx.
// ---------------------------------------------------------------------------
__global__ void __launch_bounds__(256) k3_res(
    const float* __restrict__ w_in,  const float* __restrict__ b_in,
    const float* __restrict__ rb_w1, const float* __restrict__ rb_b1,
    const float* __restrict__ rb_w2, const float* __restrict__ rb_b2,
    const float* __restrict__ w_bn,  const float* __restrict__ b_bn,
    const float* __restrict__ w_out, const float* __restrict__ b_out,
    float* __restrict__ out)
{
    __shared__ float4 s_w1[NBLK], s_w2[NBLK], s_b2[NBLK];
    __shared__ float  s_b1[NBLK];
    for (int i = threadIdx.x; i < NBLK; i += blockDim.x) {
        s_w1[i] = ((const float4*)rb_w1)[i];
        s_w2[i] = ((const float4*)rb_w2)[i];
        s_b2[i] = ((const float4*)rb_b2)[i];
        s_b1[i] = rb_b1[i];
    }
    __syncthreads();

    const int lane  = threadIdx.x & 31;
    const int warpg = (blockIdx.x * blockDim.x + threadIdx.x) >> 5;
    const int base  = warpg * 32;           // 16384 warps cover 524288 rows
    const int e     = base + lane;

    const float4 ha = *(const float4*)(g_ys + (size_t)e * 8);
    const float4 hb = *(const float4*)(g_ys + (size_t)e * 8 + 4);
    const float hv[8] = {ha.x, ha.y, ha.z, ha.w, hb.x, hb.y, hb.z, hb.w};

    float y[4];
#pragma unroll
    for (int i = 0; i < 4; i++) {
        float a = b_in[i];
#pragma unroll
        for (int j = 0; j < 8; j++) a = fmaf(w_in[i * 8 + j], hv[j], a);
        y[i] = leaky(a);
    }

#pragma unroll 2
    for (int blk = 0; blk < NBLK; blk++) {
        const float4 w1 = s_w1[blk];
        const float4 w2 = s_w2[blk];
        const float4 b2 = s_b2[blk];
        float z = s_b1[blk];
        z = fmaf(w1.x, y[0], z);
        z = fmaf(w1.y, y[1], z);
        z = fmaf(w1.z, y[2], z);
        z = fmaf(w1.w, y[3], z);
        z = leaky(z);
        y[0] = leaky(fmaf(w2.x, z, y[0]) + b2.x);
        y[1] = leaky(fmaf(w2.y, z, y[1]) + b2.y);
        y[2] = leaky(fmaf(w2.z, z, y[2]) + b2.z);
        y[3] = leaky(fmaf(w2.w, z, y[3]) + b2.w);
    }

    float yb = b_bn[0];
    yb = fmaf(w_bn[0], y[0], yb);
    yb = fmaf(w_bn[1], y[1], yb);
    yb = fmaf(w_bn[2], y[2], yb);
    yb = fmaf(w_bn[3], y[3], yb);
    yb = leaky(yb);

    // sigmoid(a*w+b) = 0.5 + 0.5*tanh(0.5*(a*w+b)) -> pre-halve w,b
    float4 wo = *(const float4*)(w_out + lane * 4);
    float4 bo = *(const float4*)(b_out + lane * 4);
    wo.x *= 0.5f; wo.y *= 0.5f; wo.z *= 0.5f; wo.w *= 0.5f;
    bo.x *= 0.5f; bo.y *= 0.5f; bo.z *= 0.5f; bo.w *= 0.5f;
    float* op = out + (size_t)base * OUTSZ + lane * 4;

#pragma unroll
    for (int cidx = 0; cidx < 32; cidx++) {
        const float ybc = __shfl_sync(0xffffffffu, yb, cidx);
        float4 o;
        o.x = fmaf(tanha(fmaf(ybc, wo.x, bo.x)), 0.5f, 0.5f);
        o.y = fmaf(tanha(fmaf(ybc, wo.y, bo.y)), 0.5f, 0.5f);
        o.z = fmaf(tanha(fmaf(ybc, wo.z, bo.z)), 0.5f, 0.5f);
        o.w = fmaf(tanha(fmaf(ybc, wo.w, bo.w)), 0.5f, 0.5f);
        *(float4*)(op + (size_t)cidx * OUTSZ) = o;
    }
}

// ---------------------------------------------------------------------------
extern "C" void kernel_launch(void* const* d_in, const int* in_sizes, int n_in,
                              void* d_out, int out_size)
{
    const float* x     = (const float*)d_in[0];
    const float* h     = (const float*)d_in[1];
    const float* c     = (const float*)d_in[2];
    const float* w_ih  = (const float*)d_in[3];
    const float* w_hh  = (const float*)d_in[4];
    const float* b_ih  = (const float*)d_in[5];
    const float* b_hh  = (const float*)d_in[6];
    const float* w_in  = (const float*)d_in[7];
    const float* b_in  = (const float*)d_in[8];
    const float* rb_w1 = (const float*)d_in[9];
    const float* rb_b1 = (const float*)d_in[10];
    const float* rb_w2 = (const float*)d_in[11];
    const float* rb_b2 = (const float*)d_in[12];
    const float* w_bn  = (const float*)d_in[13];
    const float* b_bn  = (const float*)d_in[14];
    const float* w_out = (const float*)d_in[15];
    const float* b_out = (const float*)d_in[16];
    float* out = (float*)d_out;

    k1_xw<<<2048, 256>>>(x, w_ih, b_ih, b_hh);
    k2_lstm<<<BATCH, 32>>>(h, c, w_hh, out);
    k3_res<<<2048, 256>>>(w_in, b_in, rb_w1, rb_b1, rb_w2, rb_b2,
                          w_bn, b_bn, w_out, b_out, out);
}